// round 6
// baseline (speedup 1.0000x reference)
#include <cuda_runtime.h>
#include <math.h>
#include <stdint.h>

#define BB 2
#define SS 2048
#define DD 1024
#define HH 16
#define DFF 4096
#define MTOK 4096

// ---------------- scratch (no allocations allowed) ----------------
__device__ float g_xr[(size_t)MTOK * DD];          // tf32-rounded x
__device__ float g_WpackT[(size_t)3 * DD * DD];    // [3D, D] K-major packed qkv weights (rounded)
__device__ float g_bpack[3 * DD];
__device__ float g_W1T[(size_t)DFF * DD];          // [4D, D] (rounded)
__device__ float g_W2T[(size_t)DD * DFF];          // [D, 4D] (rounded)
__device__ float g_QKV[(size_t)MTOK * 3 * DD];     // [tok, 3D] (rounded at epilogue)
__device__ float g_attn[(size_t)MTOK * DD];
__device__ float g_x1[(size_t)MTOK * DD];          // exact
__device__ float g_x1r[(size_t)MTOK * DD];         // rounded
__device__ float g_h1[(size_t)MTOK * DFF];         // rounded
__device__ float g_ffn[(size_t)MTOK * DD];

// ---------------- helpers ----------------
__device__ __forceinline__ uint32_t smem_u32(const void* p) {
    uint32_t a;
    asm("{ .reg .u64 t; cvta.to.shared.u64 t, %1; cvt.u32.u64 %0, t; }" : "=r"(a) : "l"(p));
    return a;
}
__device__ __forceinline__ float rndf(float f) {
    uint32_t u;
    asm("cvt.rna.tf32.f32 %0, %1;" : "=r"(u) : "f"(f));
    return __uint_as_float(u);
}
#define SWZ128(o) ((o) ^ (((o) >> 3) & 0x70))
#define CP16(dst, src) asm volatile("cp.async.cg.shared.global [%0], [%1], 16;" :: "r"(dst), "l"(src))
#define LDSM4(r0, r1, r2, r3, a) \
    asm volatile("ldmatrix.sync.aligned.m8n8.x4.shared.b16 {%0,%1,%2,%3}, [%4];" \
                 : "=r"(r0), "=r"(r1), "=r"(r2), "=r"(r3) : "r"(a))

__device__ __forceinline__ void mma_tf32(float* d, const uint32_t* a, const uint32_t* b) {
    asm volatile(
        "mma.sync.aligned.m16n8k8.row.col.f32.tf32.tf32.f32 "
        "{%0,%1,%2,%3}, {%4,%5,%6,%7}, {%8,%9}, {%0,%1,%2,%3};"
        : "+f"(d[0]), "+f"(d[1]), "+f"(d[2]), "+f"(d[3])
        : "r"(a[0]), "r"(a[1]), "r"(a[2]), "r"(a[3]), "r"(b[0]), "r"(b[1]));
}
__device__ __forceinline__ float ldsf(uint32_t a) {
    float v;
    asm volatile("ld.shared.f32 %0, [%1];" : "=f"(v) : "r"(a));
    return v;
}

// ================= FLASH ATTENTION =================
// grid (16 qtiles, 32 bh), block 256 (8 warps x 16 q-rows).
// SMEM float layout: Q[128][68] | K[2][128][68] | V[2][128][72] | mask[2048]
#define FAQ_BYTES 34816
#define FAK_BYTES 34816
#define FAV_BYTES 36864
#define OFF_Q 0
#define OFF_K 34816
#define OFF_V 104448
#define OFF_M 178176
#define FA_SMEM 186368

__global__ void __launch_bounds__(256, 1)
flash_attn(const float* __restrict__ QKV, const int* __restrict__ mask,
           float* __restrict__ out) {
    extern __shared__ char smem[];
    const uint32_t sb = smem_u32(smem);
    int tid = threadIdx.x, wid = tid >> 5, lid = tid & 31;
    int g = lid >> 2, tc = lid & 3;
    int r8 = lid & 7, seg = lid >> 3;
    int qt = blockIdx.x, bh = blockIdx.y;
    int b = bh >> 4, h = bh & 15;
    int q0 = qt * 128;
    int wq0 = wid * 16;
    const float* base = QKV + (size_t)b * SS * 3072 + h * 64;

    // ---- stage Q + K0 + V0 ----
#pragma unroll
    for (int i = 0; i < 8; i++) {
        int idx = tid + i * 256, r = idx >> 4, c = idx & 15;
        CP16(sb + OFF_Q + r * 272 + c * 16, base + (size_t)(q0 + r) * 3072 + c * 4);
    }
#pragma unroll
    for (int i = 0; i < 8; i++) {
        int idx = tid + i * 256, r = idx >> 4, c = idx & 15;
        CP16(sb + OFF_K + r * 272 + c * 16, base + (size_t)r * 3072 + 1024 + c * 4);
    }
#pragma unroll
    for (int i = 0; i < 8; i++) {
        int idx = tid + i * 256, r = idx >> 4, c = idx & 15;
        CP16(sb + OFF_V + r * 288 + c * 16, base + (size_t)r * 3072 + 2048 + c * 4);
    }
    asm volatile("cp.async.commit_group;" ::: "memory");
    // mask to smem
    int* msmem = (int*)(smem + OFF_M);
#pragma unroll
    for (int i = 0; i < 8; i++) {
        int idx = tid + i * 256;
        msmem[idx] = mask[b * SS + idx];
    }
    asm volatile("cp.async.wait_group 0;" ::: "memory");
    __syncthreads();

    // ---- Q fragments (persist in regs) ----
    uint32_t af[8][4];
    {
        int i8 = lid & 7, t4 = lid >> 3;
        int row = wq0 + i8 + (t4 & 1) * 8;
        uint32_t abase = sb + OFF_Q + row * 272 + (t4 >> 1) * 16;
#pragma unroll
        for (int kc = 0; kc < 8; kc++)
            LDSM4(af[kc][0], af[kc][1], af[kc][2], af[kc][3], abase + kc * 32);
    }

    float oacc[8][4];
#pragma unroll
    for (int i = 0; i < 8; i++)
#pragma unroll
        for (int j = 0; j < 4; j++) oacc[i][j] = 0.f;
    float l0 = 0.f, l1 = 0.f, m0 = -INFINITY, m1 = -INFINITY;

    for (int it = 0; it < 16; it++) {
        int buf = it & 1;
        // prefetch next K/V
        if (it + 1 < 16) {
            int kv1 = (it + 1) * 128, nb = buf ^ 1;
#pragma unroll
            for (int i = 0; i < 8; i++) {
                int idx = tid + i * 256, r = idx >> 4, c = idx & 15;
                CP16(sb + OFF_K + nb * FAK_BYTES + r * 272 + c * 16,
                     base + (size_t)(kv1 + r) * 3072 + 1024 + c * 4);
            }
#pragma unroll
            for (int i = 0; i < 8; i++) {
                int idx = tid + i * 256, r = idx >> 4, c = idx & 15;
                CP16(sb + OFF_V + nb * FAV_BYTES + r * 288 + c * 16,
                     base + (size_t)(kv1 + r) * 3072 + 2048 + c * 4);
            }
            asm volatile("cp.async.commit_group;" ::: "memory");
        }
        if (it > 0) {
            if (it + 1 < 16) asm volatile("cp.async.wait_group 1;" ::: "memory");
            else             asm volatile("cp.async.wait_group 0;" ::: "memory");
            __syncthreads();
        }

        int kv0 = it * 128;
        // ---- S = Q @ K^T : K-fragments via ldmatrix.x4 (2 n-tiles x 1 kc per LDSM) ----
        float sacc[16][4];
#pragma unroll
        for (int i = 0; i < 16; i++)
#pragma unroll
            for (int j = 0; j < 4; j++) sacc[i][j] = 0.f;
        uint32_t kb = sb + OFF_K + buf * FAK_BYTES;
#pragma unroll
        for (int np = 0; np < 8; np++) {
            int nrow = 16 * np + (seg >> 1) * 8 + r8;
            uint32_t rb = kb + nrow * 272 + (seg & 1) * 16;
#pragma unroll
            for (int kc = 0; kc < 8; kc++) {
                uint32_t bq[4];
                LDSM4(bq[0], bq[1], bq[2], bq[3], rb + kc * 32);
                mma_tf32(sacc[2 * np],     af[kc], bq);
                mma_tf32(sacc[2 * np + 1], af[kc], bq + 2);
            }
        }

        // ---- scale + mask + online softmax ----
        float mt0 = -INFINITY, mt1 = -INFINITY;
#pragma unroll
        for (int nt = 0; nt < 16; nt++) {
            int c0 = kv0 + 8 * nt + 2 * tc;
            int mk0 = msmem[c0], mk1 = msmem[c0 + 1];
            float s0 = sacc[nt][0] * 0.125f, s1 = sacc[nt][1] * 0.125f;
            float s2 = sacc[nt][2] * 0.125f, s3 = sacc[nt][3] * 0.125f;
            if (mk0 == 0) { s0 = -INFINITY; s2 = -INFINITY; }
            if (mk1 == 0) { s1 = -INFINITY; s3 = -INFINITY; }
            sacc[nt][0] = s0; sacc[nt][1] = s1; sacc[nt][2] = s2; sacc[nt][3] = s3;
            mt0 = fmaxf(mt0, fmaxf(s0, s1));
            mt1 = fmaxf(mt1, fmaxf(s2, s3));
        }
        mt0 = fmaxf(mt0, __shfl_xor_sync(0xffffffff, mt0, 1));
        mt0 = fmaxf(mt0, __shfl_xor_sync(0xffffffff, mt0, 2));
        mt1 = fmaxf(mt1, __shfl_xor_sync(0xffffffff, mt1, 1));
        mt1 = fmaxf(mt1, __shfl_xor_sync(0xffffffff, mt1, 2));
        float mn0 = fmaxf(m0, mt0), mn1 = fmaxf(m1, mt1);
        float al0 = __expf(m0 - mn0), al1 = __expf(m1 - mn1);
        l0 *= al0; l1 *= al1;
#pragma unroll
        for (int i = 0; i < 8; i++) {
            oacc[i][0] *= al0; oacc[i][1] *= al0;
            oacc[i][2] *= al1; oacc[i][3] *= al1;
        }
#pragma unroll
        for (int nt = 0; nt < 16; nt++) {
            float p0 = __expf(sacc[nt][0] - mn0);
            float p1 = __expf(sacc[nt][1] - mn0);
            float p2 = __expf(sacc[nt][2] - mn1);
            float p3 = __expf(sacc[nt][3] - mn1);
            l0 += p0 + p1; l1 += p2 + p3;
            sacc[nt][0] = rndf(p0); sacc[nt][1] = rndf(p1);
            sacc[nt][2] = rndf(p2); sacc[nt][3] = rndf(p3);
        }
        m0 = mn0; m1 = mn1;

        // ---- O += P @ V ----
        uint32_t vb = sb + OFF_V + buf * FAV_BYTES;
        int srcA = (lid & ~3) | (tc >> 1);
        int odd = tc & 1;
#pragma unroll
        for (int kc = 0; kc < 16; kc++) {
            float p0 = sacc[kc][0], p1 = sacc[kc][1], p2 = sacc[kc][2], p3 = sacc[kc][3];
            float u0 = __shfl_sync(0xffffffff, p0, srcA);
            float u1 = __shfl_sync(0xffffffff, p1, srcA);
            float w0 = __shfl_sync(0xffffffff, p2, srcA);
            float w1 = __shfl_sync(0xffffffff, p3, srcA);
            float v0 = __shfl_sync(0xffffffff, p0, srcA + 2);
            float v1 = __shfl_sync(0xffffffff, p1, srcA + 2);
            float y0 = __shfl_sync(0xffffffff, p2, srcA + 2);
            float y1 = __shfl_sync(0xffffffff, p3, srcA + 2);
            uint32_t afr[4];
            afr[0] = __float_as_uint(odd ? u1 : u0);
            afr[1] = __float_as_uint(odd ? w1 : w0);
            afr[2] = __float_as_uint(odd ? v1 : v0);
            afr[3] = __float_as_uint(odd ? y1 : y0);
            uint32_t r0b = vb + (8 * kc + tc) * 288 + g * 4;
            uint32_t r1b = vb + (8 * kc + tc + 4) * 288 + g * 4;
#pragma unroll
            for (int nt = 0; nt < 8; nt++) {
                uint32_t bf[2];
                bf[0] = __float_as_uint(ldsf(r0b + nt * 32));
                bf[1] = __float_as_uint(ldsf(r1b + nt * 32));
                mma_tf32(oacc[nt], afr, bf);
            }
        }
        __syncthreads();
    }

    // ---- reduce l across quad (each lane held partial sums of its own cols) ----
    l0 += __shfl_xor_sync(0xffffffff, l0, 1);
    l0 += __shfl_xor_sync(0xffffffff, l0, 2);
    l1 += __shfl_xor_sync(0xffffffff, l1, 1);
    l1 += __shfl_xor_sync(0xffffffff, l1, 2);

    // ---- epilogue: O / l -> attn [tok, D] ----
    float il0 = 1.f / l0, il1 = 1.f / l1;
    int r0 = q0 + wq0 + g, r1 = r0 + 8;
    float* o0 = out + (size_t)(b * SS + r0) * DD + h * 64 + 2 * tc;
    float* o1 = out + (size_t)(b * SS + r1) * DD + h * 64 + 2 * tc;
#pragma unroll
    for (int nt = 0; nt < 8; nt++) {
        *(float2*)(o0 + nt * 8) = make_float2(oacc[nt][0] * il0, oacc[nt][1] * il0);
        *(float2*)(o1 + nt * 8) = make_float2(oacc[nt][2] * il1, oacc[nt][3] * il1);
    }
}

// ---------------- tf32 mma.sync GEMM ----------------
// C[M,N] = A[M,K] @ B[N,K]^T + epilogue.  MODE 0: +bias  1: relu(+bias)
template <int BN, int MODE, bool RND>
__global__ void __launch_bounds__(256)
mma_gemm(const float* __restrict__ A, int lda,
         const float* __restrict__ B, int ldb,
         float* __restrict__ C, int ldc,
         const float* __restrict__ bias, int K) {
    extern __shared__ char smem[];
    constexpr int ABYTES = 128 * 32 * 4;
    constexpr int BBYTES = BN * 32 * 4;
    constexpr int MT = 4;

    const uint32_t sb = smem_u32(smem);
    int tid = threadIdx.x, wid = tid >> 5, lid = tid & 31;
    int m0 = blockIdx.y * 128, n0 = blockIdx.x * BN;

    int wm0 = (wid >> 2) * 64, wn0 = (wid & 3) * 32;

    float acc[MT][4][4];
#pragma unroll
    for (int i = 0; i < MT; i++)
#pragma unroll
        for (int j = 0; j < 4; j++)
#pragma unroll
            for (int r = 0; r < 4; r++) acc[i][j][r] = 0.f;

    const int NC = K >> 5;
    {
        uint32_t ab = sb, bb = sb + 2 * ABYTES;
#pragma unroll
        for (int i = 0; i < 4; i++) {
            int q = tid + i * 256, row = q >> 3, cg = q & 7;
            CP16(ab + SWZ128(q * 16), A + (size_t)(m0 + row) * lda + cg * 4);
        }
#pragma unroll
        for (int i = 0; i < (BN * 8) / 256; i++) {
            int q = tid + i * 256, row = q >> 3, cg = q & 7;
            CP16(bb + SWZ128(q * 16), B + (size_t)(n0 + row) * ldb + cg * 4);
        }
        asm volatile("cp.async.commit_group;" ::: "memory");
    }

    for (int c = 0; c < NC; c++) {
        int buf = c & 1;
        if (c + 1 < NC) {
            int k0 = (c + 1) << 5;
            uint32_t ab = sb + (buf ^ 1) * ABYTES;
            uint32_t bb = sb + 2 * ABYTES + (buf ^ 1) * BBYTES;
#pragma unroll
            for (int i = 0; i < 4; i++) {
                int q = tid + i * 256, row = q >> 3, cg = q & 7;
                CP16(ab + SWZ128(q * 16), A + (size_t)(m0 + row) * lda + k0 + cg * 4);
            }
#pragma unroll
            for (int i = 0; i < (BN * 8) / 256; i++) {
                int q = tid + i * 256, row = q >> 3, cg = q & 7;
                CP16(bb + SWZ128(q * 16), B + (size_t)(n0 + row) * ldb + k0 + cg * 4);
            }
            asm volatile("cp.async.commit_group;" ::: "memory");
            asm volatile("cp.async.wait_group 1;" ::: "memory");
        } else {
            asm volatile("cp.async.wait_group 0;" ::: "memory");
        }
        __syncthreads();

        uint32_t ab = sb + buf * ABYTES;
        uint32_t bb = sb + 2 * ABYTES + buf * BBYTES;
        int i8 = lid & 7, t4 = lid >> 3;
        int r8 = lid & 7, seg = lid >> 3;
#pragma unroll
        for (int s = 0; s < 4; s++) {
            uint32_t af[MT][4];
#pragma unroll
            for (int mt = 0; mt < MT; mt++) {
                int row = wm0 + mt * 16 + i8 + (t4 & 1) * 8;
                uint32_t addr = ab + SWZ128(row * 128 + (2 * s + (t4 >> 1)) * 16);
                LDSM4(af[mt][0], af[mt][1], af[mt][2], af[mt][3], addr);
            }
            // B fragments via ldmatrix.x4: 2 n-tiles per LDSM
            uint32_t bfr[8];
            {
                int nrow = wn0 + (seg >> 1) * 8 + r8;
                uint32_t a0 = bb + SWZ128(nrow * 128 + s * 32 + (seg & 1) * 16);
                uint32_t a1 = bb + SWZ128((nrow + 16) * 128 + s * 32 + (seg & 1) * 16);
                LDSM4(bfr[0], bfr[1], bfr[2], bfr[3], a0);
                LDSM4(bfr[4], bfr[5], bfr[6], bfr[7], a1);
            }
#pragma unroll
            for (int mt = 0; mt < MT; mt++)
#pragma unroll
                for (int nt = 0; nt < 4; nt++)
                    mma_tf32(acc[mt][nt], af[mt], bfr + 2 * nt);
        }
        __syncthreads();
    }

    int g = lid >> 2, tc = lid & 3;
#pragma unroll
    for (int mt = 0; mt < MT; mt++) {
        int row = m0 + wm0 + mt * 16 + g;
#pragma unroll
        for (int nt = 0; nt < 4; nt++) {
            int col = n0 + wn0 + nt * 8 + tc * 2;
            float v00 = acc[mt][nt][0], v01 = acc[mt][nt][1];
            float v10 = acc[mt][nt][2], v11 = acc[mt][nt][3];
            float2 bv = *(const float2*)(bias + col);
            v00 += bv.x; v01 += bv.y; v10 += bv.x; v11 += bv.y;
            if (MODE == 1) {
                v00 = fmaxf(v00, 0.f); v01 = fmaxf(v01, 0.f);
                v10 = fmaxf(v10, 0.f); v11 = fmaxf(v11, 0.f);
            }
            if (RND) {
                v00 = rndf(v00); v01 = rndf(v01); v10 = rndf(v10); v11 = rndf(v11);
            }
            *(float2*)(C + (size_t)row * ldc + col) = make_float2(v00, v01);
            *(float2*)(C + (size_t)(row + 8) * ldc + col) = make_float2(v10, v11);
        }
    }
}

// ---------------- prep kernels ----------------
__global__ void round_copy(const float* __restrict__ in, float* __restrict__ out, int n4) {
    int i = blockIdx.x * blockDim.x + threadIdx.x;
    if (i < n4) {
        float4 v = ((const float4*)in)[i];
        v.x = rndf(v.x); v.y = rndf(v.y); v.z = rndf(v.z); v.w = rndf(v.w);
        ((float4*)out)[i] = v;
    }
}

__global__ void pack_wT(const float* __restrict__ Wq, const float* __restrict__ Wk,
                        const float* __restrict__ Wv) {
    __shared__ float t[32][33];
    int zz = blockIdx.z;
    int which = zz / HH, h = zz % HH;
    const float* W = (which == 0) ? Wq : (which == 1) ? Wk : Wv;
    int d0 = blockIdx.x * 32, e0 = blockIdx.y * 32;
#pragma unroll
    for (int i = 0; i < 32; i += 8)
        t[threadIdx.y + i][threadIdx.x] =
            W[(size_t)h * (DD * 64) + (size_t)(d0 + threadIdx.y + i) * 64 + e0 + threadIdx.x];
    __syncthreads();
#pragma unroll
    for (int i = 0; i < 32; i += 8)
        g_WpackT[(size_t)(which * DD + h * 64 + e0 + threadIdx.y + i) * DD + d0 + threadIdx.x] =
            rndf(t[threadIdx.x][threadIdx.y + i]);
}

__global__ void pack_bias(const float* __restrict__ bq, const float* __restrict__ bk,
                          const float* __restrict__ bv) {
    int i = blockIdx.x * blockDim.x + threadIdx.x;
    if (i < 3 * DD) {
        int which = i / DD, c = i % DD;
        const float* b = (which == 0) ? bq : (which == 1) ? bk : bv;
        g_bpack[i] = b[c];
    }
}

__global__ void transpose_k(const float* __restrict__ in, float* __restrict__ out, int R, int C) {
    __shared__ float t[32][33];
    int c0 = blockIdx.x * 32, r0 = blockIdx.y * 32;
#pragma unroll
    for (int i = 0; i < 32; i += 8)
        t[threadIdx.y + i][threadIdx.x] = in[(size_t)(r0 + threadIdx.y + i) * C + c0 + threadIdx.x];
    __syncthreads();
#pragma unroll
    for (int i = 0; i < 32; i += 8)
        out[(size_t)(c0 + threadIdx.y + i) * R + r0 + threadIdx.x] = rndf(t[threadIdx.x][threadIdx.y + i]);
}

// ---------------- out = xres + alpha*(a-mean)/(std_unbiased+eps) + beta ----------------
template <bool DUAL>
__global__ void add_ln(const float* __restrict__ xres, const float* __restrict__ a,
                       const float* __restrict__ alpha, const float* __restrict__ beta,
                       float* __restrict__ out, float* __restrict__ outr) {
    int row = blockIdx.x;
    int tid = threadIdx.x;
    const float* ap = a + (size_t)row * DD;
    float v[4];
    float lsum = 0.f;
#pragma unroll
    for (int i = 0; i < 4; i++) {
        v[i] = ap[tid + i * 256];
        lsum += v[i];
    }
    __shared__ float red[256];
    red[tid] = lsum;
    __syncthreads();
    for (int s = 128; s > 0; s >>= 1) {
        if (tid < s) red[tid] += red[tid + s];
        __syncthreads();
    }
    float mean = red[0] * (1.f / DD);
    __syncthreads();
    float lss = 0.f;
#pragma unroll
    for (int i = 0; i < 4; i++) {
        float d = v[i] - mean;
        lss += d * d;
    }
    red[tid] = lss;
    __syncthreads();
    for (int s = 128; s > 0; s >>= 1) {
        if (tid < s) red[tid] += red[tid + s];
        __syncthreads();
    }
    float var = red[0] * (1.f / (DD - 1));
    float inv = 1.f / (sqrtf(var) + 1e-6f);
#pragma unroll
    for (int i = 0; i < 4; i++) {
        int c = tid + i * 256;
        float o = xres[(size_t)row * DD + c] + alpha[c] * (v[i] - mean) * inv + beta[c];
        out[(size_t)row * DD + c] = o;
        if (DUAL) outr[(size_t)row * DD + c] = rndf(o);
    }
}

// ---------------- launch ----------------
extern "C" void kernel_launch(void* const* d_in, const int* in_sizes, int n_in,
                              void* d_out, int out_size) {
    const float* x      = (const float*)d_in[0];
    const int*   mask   = (const int*)d_in[1];
    const float* Wq     = (const float*)d_in[2];
    const float* bq     = (const float*)d_in[3];
    const float* Wk     = (const float*)d_in[4];
    const float* bk     = (const float*)d_in[5];
    const float* Wv     = (const float*)d_in[6];
    const float* bv     = (const float*)d_in[7];
    const float* W1     = (const float*)d_in[8];
    const float* b1     = (const float*)d_in[9];
    const float* W2     = (const float*)d_in[10];
    const float* b2     = (const float*)d_in[11];
    const float* alpha1 = (const float*)d_in[12];
    const float* beta1  = (const float*)d_in[13];
    const float* alpha2 = (const float*)d_in[14];
    const float* beta2  = (const float*)d_in[15];
    float* out = (float*)d_out;

    float *xr, *WpackT, *bpack, *W1T, *W2T, *QKV, *attn, *x1, *x1r, *h1, *ffn;
    cudaGetSymbolAddress((void**)&xr,     g_xr);
    cudaGetSymbolAddress((void**)&WpackT, g_WpackT);
    cudaGetSymbolAddress((void**)&bpack,  g_bpack);
    cudaGetSymbolAddress((void**)&W1T,    g_W1T);
    cudaGetSymbolAddress((void**)&W2T,    g_W2T);
    cudaGetSymbolAddress((void**)&QKV,    g_QKV);
    cudaGetSymbolAddress((void**)&attn,   g_attn);
    cudaGetSymbolAddress((void**)&x1,     g_x1);
    cudaGetSymbolAddress((void**)&x1r,    g_x1r);
    cudaGetSymbolAddress((void**)&h1,     g_h1);
    cudaGetSymbolAddress((void**)&ffn,    g_ffn);

    const int SM128 = 2 * 16384 + 2 * 128 * 32 * 4;   // 65536
    cudaFuncSetAttribute(mma_gemm<128, 0, true>,  cudaFuncAttributeMaxDynamicSharedMemorySize, SM128);
    cudaFuncSetAttribute(mma_gemm<128, 0, false>, cudaFuncAttributeMaxDynamicSharedMemorySize, SM128);
    cudaFuncSetAttribute(mma_gemm<128, 1, true>,  cudaFuncAttributeMaxDynamicSharedMemorySize, SM128);
    cudaFuncSetAttribute(flash_attn, cudaFuncAttributeMaxDynamicSharedMemorySize, FA_SMEM);

    // prep
    round_copy<<<(MTOK * DD / 4 + 255) / 256, 256>>>(x, xr, MTOK * DD / 4);
    pack_wT<<<dim3(32, 2, 48), dim3(32, 8)>>>(Wq, Wk, Wv);
    pack_bias<<<12, 256>>>(bq, bk, bv);
    transpose_k<<<dim3(DFF / 32, DD / 32), dim3(32, 8)>>>(W1, W1T, DD, DFF);
    transpose_k<<<dim3(DD / 32, DFF / 32), dim3(32, 8)>>>(W2, W2T, DFF, DD);

    // QKV = xr @ WpackT^T + bias  [4096, 3072], rounded
    mma_gemm<128, 0, true><<<dim3(24, 32), 256, SM128>>>(
        xr, DD, WpackT, DD, QKV, 3 * DD, bpack, DD);

    // fused attention: scores + mask + softmax + P@V
    flash_attn<<<dim3(16, 32), 256, FA_SMEM>>>(QKV, mask, attn);

    // x1 = x + LN1(attn)  (exact + rounded copy)
    add_ln<true><<<MTOK, 256>>>(x, attn, alpha1, beta1, x1, x1r);

    // FFN1: relu(x1r @ W1 + b1), rounded
    mma_gemm<128, 1, true><<<dim3(32, 32), 256, SM128>>>(
        x1r, DD, W1T, DD, h1, DFF, b1, DD);

    // FFN2: h1 @ W2 + b2
    mma_gemm<128, 0, false><<<dim3(8, 32), 256, SM128>>>(
        h1, DFF, W2T, DFF, ffn, DD, b2, DFF);

    // out = x1 + LN2(ffn)
    add_ln<false><<<MTOK, 256>>>(x1, ffn, alpha2, beta2, out, nullptr);
}

// round 7
// speedup vs baseline: 1.0110x; 1.0110x over previous
#include <cuda_runtime.h>
#include <math.h>
#include <stdint.h>

#define BB 2
#define SS 2048
#define DD 1024
#define HH 16
#define DFF 4096
#define MTOK 4096

// ---------------- scratch (no allocations allowed) ----------------
__device__ float g_xr[(size_t)MTOK * DD];          // tf32-rounded x
__device__ float g_WpackT[(size_t)3 * DD * DD];    // [3D, D] K-major packed qkv weights (rounded)
__device__ float g_bpack[3 * DD];
__device__ float g_W1T[(size_t)DFF * DD];          // [4D, D] (rounded)
__device__ float g_W2T[(size_t)DD * DFF];          // [D, 4D] (rounded)
__device__ float g_QKV[(size_t)MTOK * 3 * DD];     // [tok, 3D] (rounded at epilogue)
__device__ float g_attn[(size_t)MTOK * DD];
__device__ float g_x1[(size_t)MTOK * DD];          // exact
__device__ float g_x1r[(size_t)MTOK * DD];         // rounded
__device__ float g_h1[(size_t)MTOK * DFF];         // rounded
__device__ float g_ffn[(size_t)MTOK * DD];

// ---------------- helpers ----------------
__device__ __forceinline__ uint32_t smem_u32(const void* p) {
    uint32_t a;
    asm("{ .reg .u64 t; cvta.to.shared.u64 t, %1; cvt.u32.u64 %0, t; }" : "=r"(a) : "l"(p));
    return a;
}
__device__ __forceinline__ float rndf(float f) {
    uint32_t u;
    asm("cvt.rna.tf32.f32 %0, %1;" : "=r"(u) : "f"(f));
    return __uint_as_float(u);
}
#define SWZ128(o) ((o) ^ (((o) >> 3) & 0x70))
#define CP16(dst, src) asm volatile("cp.async.cg.shared.global [%0], [%1], 16;" :: "r"(dst), "l"(src))
#define LDSM4(r0, r1, r2, r3, a) \
    asm volatile("ldmatrix.sync.aligned.m8n8.x4.shared.b16 {%0,%1,%2,%3}, [%4];" \
                 : "=r"(r0), "=r"(r1), "=r"(r2), "=r"(r3) : "r"(a))

__device__ __forceinline__ void mma_tf32(float* d, const uint32_t* a, const uint32_t* b) {
    asm volatile(
        "mma.sync.aligned.m16n8k8.row.col.f32.tf32.tf32.f32 "
        "{%0,%1,%2,%3}, {%4,%5,%6,%7}, {%8,%9}, {%0,%1,%2,%3};"
        : "+f"(d[0]), "+f"(d[1]), "+f"(d[2]), "+f"(d[3])
        : "r"(a[0]), "r"(a[1]), "r"(a[2]), "r"(a[3]), "r"(b[0]), "r"(b[1]));
}
__device__ __forceinline__ float ldsf(uint32_t a) {
    float v;
    asm volatile("ld.shared.f32 %0, [%1];" : "=f"(v) : "r"(a));
    return v;
}

// ================= FLASH ATTENTION (256 q-rows / CTA, two halves vs resident K/V) =================
// grid (8 qtiles, 32 bh), block 256 (8 warps x 16 q-rows x 2 halves).
// SMEM float layout: Q[256][68] | K[2][128][68] | V[2][128][72] | mask[2048]
#define FAK_BYTES 34816
#define FAV_BYTES 36864
#define OFF_Q 0
#define OFF_K 69632
#define OFF_V 139264
#define OFF_M 212992
#define FA_SMEM 221184

__global__ void __launch_bounds__(256, 1)
flash_attn(const float* __restrict__ QKV, const int* __restrict__ mask,
           float* __restrict__ out) {
    extern __shared__ char smem[];
    const uint32_t sb = smem_u32(smem);
    int tid = threadIdx.x, wid = tid >> 5, lid = tid & 31;
    int g = lid >> 2, tc = lid & 3;
    int r8 = lid & 7, seg = lid >> 3;
    int qt = blockIdx.x, bh = blockIdx.y;
    int b = bh >> 4, h = bh & 15;
    int q0 = qt * 256;
    int wq0 = wid * 16;
    const float* base = QKV + (size_t)b * SS * 3072 + h * 64;

    // ---- stage Q (256 rows) + K0 + V0 ----
#pragma unroll
    for (int i = 0; i < 16; i++) {
        int idx = tid + i * 256, r = idx >> 4, c = idx & 15;
        CP16(sb + OFF_Q + r * 272 + c * 16, base + (size_t)(q0 + r) * 3072 + c * 4);
    }
#pragma unroll
    for (int i = 0; i < 8; i++) {
        int idx = tid + i * 256, r = idx >> 4, c = idx & 15;
        CP16(sb + OFF_K + r * 272 + c * 16, base + (size_t)r * 3072 + 1024 + c * 4);
    }
#pragma unroll
    for (int i = 0; i < 8; i++) {
        int idx = tid + i * 256, r = idx >> 4, c = idx & 15;
        CP16(sb + OFF_V + r * 288 + c * 16, base + (size_t)r * 3072 + 2048 + c * 4);
    }
    asm volatile("cp.async.commit_group;" ::: "memory");
    // mask to smem
    int* msmem = (int*)(smem + OFF_M);
#pragma unroll
    for (int i = 0; i < 8; i++) {
        int idx = tid + i * 256;
        msmem[idx] = mask[b * SS + idx];
    }
    asm volatile("cp.async.wait_group 0;" ::: "memory");
    __syncthreads();

    // ---- Q fragments for both halves (persist in regs) ----
    uint32_t af[2][8][4];
    {
        int i8 = lid & 7, t4 = lid >> 3;
#pragma unroll
        for (int hf = 0; hf < 2; hf++) {
            int row = hf * 128 + wq0 + i8 + (t4 & 1) * 8;
            uint32_t abase = sb + OFF_Q + row * 272 + (t4 >> 1) * 16;
#pragma unroll
            for (int kc = 0; kc < 8; kc++)
                LDSM4(af[hf][kc][0], af[hf][kc][1], af[hf][kc][2], af[hf][kc][3],
                      abase + kc * 32);
        }
    }

    float oacc[2][8][4];
#pragma unroll
    for (int hf = 0; hf < 2; hf++)
#pragma unroll
        for (int i = 0; i < 8; i++)
#pragma unroll
            for (int j = 0; j < 4; j++) oacc[hf][i][j] = 0.f;
    float ll[2][2] = {{0.f, 0.f}, {0.f, 0.f}};
    float mm[2][2] = {{-INFINITY, -INFINITY}, {-INFINITY, -INFINITY}};

    for (int it = 0; it < 16; it++) {
        int buf = it & 1;
        // prefetch next K/V
        if (it + 1 < 16) {
            int kv1 = (it + 1) * 128, nb = buf ^ 1;
#pragma unroll
            for (int i = 0; i < 8; i++) {
                int idx = tid + i * 256, r = idx >> 4, c = idx & 15;
                CP16(sb + OFF_K + nb * FAK_BYTES + r * 272 + c * 16,
                     base + (size_t)(kv1 + r) * 3072 + 1024 + c * 4);
            }
#pragma unroll
            for (int i = 0; i < 8; i++) {
                int idx = tid + i * 256, r = idx >> 4, c = idx & 15;
                CP16(sb + OFF_V + nb * FAV_BYTES + r * 288 + c * 16,
                     base + (size_t)(kv1 + r) * 3072 + 2048 + c * 4);
            }
            asm volatile("cp.async.commit_group;" ::: "memory");
        }
        if (it > 0) {
            if (it + 1 < 16) asm volatile("cp.async.wait_group 1;" ::: "memory");
            else             asm volatile("cp.async.wait_group 0;" ::: "memory");
            __syncthreads();
        }

        int kv0 = it * 128;
        uint32_t kb = sb + OFF_K + buf * FAK_BYTES;
        uint32_t vb = sb + OFF_V + buf * FAV_BYTES;

#pragma unroll
        for (int hf = 0; hf < 2; hf++) {
            // ---- S = Q @ K^T ----
            float sacc[16][4];
#pragma unroll
            for (int i = 0; i < 16; i++)
#pragma unroll
                for (int j = 0; j < 4; j++) sacc[i][j] = 0.f;
#pragma unroll
            for (int np = 0; np < 8; np++) {
                int nrow = 16 * np + (seg >> 1) * 8 + r8;
                uint32_t rb = kb + nrow * 272 + (seg & 1) * 16;
#pragma unroll
                for (int kc = 0; kc < 8; kc++) {
                    uint32_t bq[4];
                    LDSM4(bq[0], bq[1], bq[2], bq[3], rb + kc * 32);
                    mma_tf32(sacc[2 * np],     af[hf][kc], bq);
                    mma_tf32(sacc[2 * np + 1], af[hf][kc], bq + 2);
                }
            }

            // ---- scale + mask + online softmax ----
            float mt0 = -INFINITY, mt1 = -INFINITY;
#pragma unroll
            for (int nt = 0; nt < 16; nt++) {
                int c0 = kv0 + 8 * nt + 2 * tc;
                int mk0 = msmem[c0], mk1 = msmem[c0 + 1];
                float s0 = sacc[nt][0] * 0.125f, s1 = sacc[nt][1] * 0.125f;
                float s2 = sacc[nt][2] * 0.125f, s3 = sacc[nt][3] * 0.125f;
                if (mk0 == 0) { s0 = -INFINITY; s2 = -INFINITY; }
                if (mk1 == 0) { s1 = -INFINITY; s3 = -INFINITY; }
                sacc[nt][0] = s0; sacc[nt][1] = s1; sacc[nt][2] = s2; sacc[nt][3] = s3;
                mt0 = fmaxf(mt0, fmaxf(s0, s1));
                mt1 = fmaxf(mt1, fmaxf(s2, s3));
            }
            mt0 = fmaxf(mt0, __shfl_xor_sync(0xffffffff, mt0, 1));
            mt0 = fmaxf(mt0, __shfl_xor_sync(0xffffffff, mt0, 2));
            mt1 = fmaxf(mt1, __shfl_xor_sync(0xffffffff, mt1, 1));
            mt1 = fmaxf(mt1, __shfl_xor_sync(0xffffffff, mt1, 2));
            float mn0 = fmaxf(mm[hf][0], mt0), mn1 = fmaxf(mm[hf][1], mt1);
            float al0 = __expf(mm[hf][0] - mn0), al1 = __expf(mm[hf][1] - mn1);
            ll[hf][0] *= al0; ll[hf][1] *= al1;
#pragma unroll
            for (int i = 0; i < 8; i++) {
                oacc[hf][i][0] *= al0; oacc[hf][i][1] *= al0;
                oacc[hf][i][2] *= al1; oacc[hf][i][3] *= al1;
            }
#pragma unroll
            for (int nt = 0; nt < 16; nt++) {
                float p0 = __expf(sacc[nt][0] - mn0);
                float p1 = __expf(sacc[nt][1] - mn0);
                float p2 = __expf(sacc[nt][2] - mn1);
                float p3 = __expf(sacc[nt][3] - mn1);
                ll[hf][0] += p0 + p1; ll[hf][1] += p2 + p3;
                sacc[nt][0] = rndf(p0); sacc[nt][1] = rndf(p1);
                sacc[nt][2] = rndf(p2); sacc[nt][3] = rndf(p3);
            }
            mm[hf][0] = mn0; mm[hf][1] = mn1;

            // ---- O += P @ V ----
            int srcA = (lid & ~3) | (tc >> 1);
            int odd = tc & 1;
#pragma unroll
            for (int kc = 0; kc < 16; kc++) {
                float p0 = sacc[kc][0], p1 = sacc[kc][1], p2 = sacc[kc][2], p3 = sacc[kc][3];
                float u0 = __shfl_sync(0xffffffff, p0, srcA);
                float u1 = __shfl_sync(0xffffffff, p1, srcA);
                float w0 = __shfl_sync(0xffffffff, p2, srcA);
                float w1 = __shfl_sync(0xffffffff, p3, srcA);
                float v0 = __shfl_sync(0xffffffff, p0, srcA + 2);
                float v1 = __shfl_sync(0xffffffff, p1, srcA + 2);
                float y0 = __shfl_sync(0xffffffff, p2, srcA + 2);
                float y1 = __shfl_sync(0xffffffff, p3, srcA + 2);
                uint32_t afr[4];
                afr[0] = __float_as_uint(odd ? u1 : u0);
                afr[1] = __float_as_uint(odd ? w1 : w0);
                afr[2] = __float_as_uint(odd ? v1 : v0);
                afr[3] = __float_as_uint(odd ? y1 : y0);
                uint32_t r0b = vb + (8 * kc + tc) * 288 + g * 4;
                uint32_t r1b = vb + (8 * kc + tc + 4) * 288 + g * 4;
#pragma unroll
                for (int nt = 0; nt < 8; nt++) {
                    uint32_t bf[2];
                    bf[0] = __float_as_uint(ldsf(r0b + nt * 32));
                    bf[1] = __float_as_uint(ldsf(r1b + nt * 32));
                    mma_tf32(oacc[hf][nt], afr, bf);
                }
            }
        }
        __syncthreads();
    }

    // ---- reduce l across quad, write both halves ----
#pragma unroll
    for (int hf = 0; hf < 2; hf++) {
        float l0 = ll[hf][0], l1 = ll[hf][1];
        l0 += __shfl_xor_sync(0xffffffff, l0, 1);
        l0 += __shfl_xor_sync(0xffffffff, l0, 2);
        l1 += __shfl_xor_sync(0xffffffff, l1, 1);
        l1 += __shfl_xor_sync(0xffffffff, l1, 2);
        float il0 = 1.f / l0, il1 = 1.f / l1;
        int r0 = q0 + hf * 128 + wq0 + g, r1 = r0 + 8;
        float* o0 = out + (size_t)(b * SS + r0) * DD + h * 64 + 2 * tc;
        float* o1 = out + (size_t)(b * SS + r1) * DD + h * 64 + 2 * tc;
#pragma unroll
        for (int nt = 0; nt < 8; nt++) {
            *(float2*)(o0 + nt * 8) = make_float2(oacc[hf][nt][0] * il0, oacc[hf][nt][1] * il0);
            *(float2*)(o1 + nt * 8) = make_float2(oacc[hf][nt][2] * il1, oacc[hf][nt][3] * il1);
        }
    }
}

// ---------------- tf32 mma.sync GEMM: 256x128 tile, 512 threads ----------------
// C[M,N] = A[M,K] @ B[N,K]^T + epilogue.  MODE 0: +bias  1: relu(+bias)
#define GA_BYTES 32768
#define GB_BYTES 16384
#define G_SMEM (2 * GA_BYTES + 2 * GB_BYTES)

template <int MODE, bool RND>
__global__ void __launch_bounds__(512)
mma_gemm(const float* __restrict__ A, int lda,
         const float* __restrict__ B, int ldb,
         float* __restrict__ C, int ldc,
         const float* __restrict__ bias, int K) {
    extern __shared__ char smem[];
    constexpr int MT = 4;

    const uint32_t sb = smem_u32(smem);
    int tid = threadIdx.x, wid = tid >> 5, lid = tid & 31;
    int m0 = blockIdx.y * 256, n0 = blockIdx.x * 128;

    int wm0 = (wid >> 2) * 64, wn0 = (wid & 3) * 32;

    float acc[MT][4][4];
#pragma unroll
    for (int i = 0; i < MT; i++)
#pragma unroll
        for (int j = 0; j < 4; j++)
#pragma unroll
            for (int r = 0; r < 4; r++) acc[i][j][r] = 0.f;

    const int NC = K >> 5;
    {
        uint32_t ab = sb, bb = sb + 2 * GA_BYTES;
#pragma unroll
        for (int i = 0; i < 4; i++) {
            int q = tid + i * 512, row = q >> 3, cg = q & 7;
            CP16(ab + SWZ128(q * 16), A + (size_t)(m0 + row) * lda + cg * 4);
        }
#pragma unroll
        for (int i = 0; i < 2; i++) {
            int q = tid + i * 512, row = q >> 3, cg = q & 7;
            CP16(bb + SWZ128(q * 16), B + (size_t)(n0 + row) * ldb + cg * 4);
        }
        asm volatile("cp.async.commit_group;" ::: "memory");
    }

    for (int c = 0; c < NC; c++) {
        int buf = c & 1;
        if (c + 1 < NC) {
            int k0 = (c + 1) << 5;
            uint32_t ab = sb + (buf ^ 1) * GA_BYTES;
            uint32_t bb = sb + 2 * GA_BYTES + (buf ^ 1) * GB_BYTES;
#pragma unroll
            for (int i = 0; i < 4; i++) {
                int q = tid + i * 512, row = q >> 3, cg = q & 7;
                CP16(ab + SWZ128(q * 16), A + (size_t)(m0 + row) * lda + k0 + cg * 4);
            }
#pragma unroll
            for (int i = 0; i < 2; i++) {
                int q = tid + i * 512, row = q >> 3, cg = q & 7;
                CP16(bb + SWZ128(q * 16), B + (size_t)(n0 + row) * ldb + k0 + cg * 4);
            }
            asm volatile("cp.async.commit_group;" ::: "memory");
            asm volatile("cp.async.wait_group 1;" ::: "memory");
        } else {
            asm volatile("cp.async.wait_group 0;" ::: "memory");
        }
        __syncthreads();

        uint32_t ab = sb + buf * GA_BYTES;
        uint32_t bb = sb + 2 * GA_BYTES + buf * GB_BYTES;
        int i8 = lid & 7, t4 = lid >> 3;
        int r8 = lid & 7, seg = lid >> 3;
#pragma unroll
        for (int s = 0; s < 4; s++) {
            uint32_t af[MT][4];
#pragma unroll
            for (int mt = 0; mt < MT; mt++) {
                int row = wm0 + mt * 16 + i8 + (t4 & 1) * 8;
                uint32_t addr = ab + SWZ128(row * 128 + (2 * s + (t4 >> 1)) * 16);
                LDSM4(af[mt][0], af[mt][1], af[mt][2], af[mt][3], addr);
            }
            // B fragments via ldmatrix.x4: 2 n-tiles per LDSM
            uint32_t bfr[8];
            {
                int nrow = wn0 + (seg >> 1) * 8 + r8;
                uint32_t a0 = bb + SWZ128(nrow * 128 + s * 32 + (seg & 1) * 16);
                uint32_t a1 = bb + SWZ128((nrow + 16) * 128 + s * 32 + (seg & 1) * 16);
                LDSM4(bfr[0], bfr[1], bfr[2], bfr[3], a0);
                LDSM4(bfr[4], bfr[5], bfr[6], bfr[7], a1);
            }
#pragma unroll
            for (int mt = 0; mt < MT; mt++)
#pragma unroll
                for (int nt = 0; nt < 4; nt++)
                    mma_tf32(acc[mt][nt], af[mt], bfr + 2 * nt);
        }
        __syncthreads();
    }

    int g = lid >> 2, tc = lid & 3;
#pragma unroll
    for (int mt = 0; mt < MT; mt++) {
        int row = m0 + wm0 + mt * 16 + g;
#pragma unroll
        for (int nt = 0; nt < 4; nt++) {
            int col = n0 + wn0 + nt * 8 + tc * 2;
            float v00 = acc[mt][nt][0], v01 = acc[mt][nt][1];
            float v10 = acc[mt][nt][2], v11 = acc[mt][nt][3];
            float2 bv = *(const float2*)(bias + col);
            v00 += bv.x; v01 += bv.y; v10 += bv.x; v11 += bv.y;
            if (MODE == 1) {
                v00 = fmaxf(v00, 0.f); v01 = fmaxf(v01, 0.f);
                v10 = fmaxf(v10, 0.f); v11 = fmaxf(v11, 0.f);
            }
            if (RND) {
                v00 = rndf(v00); v01 = rndf(v01); v10 = rndf(v10); v11 = rndf(v11);
            }
            *(float2*)(C + (size_t)row * ldc + col) = make_float2(v00, v01);
            *(float2*)(C + (size_t)(row + 8) * ldc + col) = make_float2(v10, v11);
        }
    }
}

// ---------------- prep kernels ----------------
__global__ void round_copy(const float* __restrict__ in, float* __restrict__ out, int n4) {
    int i = blockIdx.x * blockDim.x + threadIdx.x;
    if (i < n4) {
        float4 v = ((const float4*)in)[i];
        v.x = rndf(v.x); v.y = rndf(v.y); v.z = rndf(v.z); v.w = rndf(v.w);
        ((float4*)out)[i] = v;
    }
}

__global__ void pack_wT(const float* __restrict__ Wq, const float* __restrict__ Wk,
                        const float* __restrict__ Wv) {
    __shared__ float t[32][33];
    int zz = blockIdx.z;
    int which = zz / HH, h = zz % HH;
    const float* W = (which == 0) ? Wq : (which == 1) ? Wk : Wv;
    int d0 = blockIdx.x * 32, e0 = blockIdx.y * 32;
#pragma unroll
    for (int i = 0; i < 32; i += 8)
        t[threadIdx.y + i][threadIdx.x] =
            W[(size_t)h * (DD * 64) + (size_t)(d0 + threadIdx.y + i) * 64 + e0 + threadIdx.x];
    __syncthreads();
#pragma unroll
    for (int i = 0; i < 32; i += 8)
        g_WpackT[(size_t)(which * DD + h * 64 + e0 + threadIdx.y + i) * DD + d0 + threadIdx.x] =
            rndf(t[threadIdx.x][threadIdx.y + i]);
}

__global__ void pack_bias(const float* __restrict__ bq, const float* __restrict__ bk,
                          const float* __restrict__ bv) {
    int i = blockIdx.x * blockDim.x + threadIdx.x;
    if (i < 3 * DD) {
        int which = i / DD, c = i % DD;
        const float* b = (which == 0) ? bq : (which == 1) ? bk : bv;
        g_bpack[i] = b[c];
    }
}

__global__ void transpose_k(const float* __restrict__ in, float* __restrict__ out, int R, int C) {
    __shared__ float t[32][33];
    int c0 = blockIdx.x * 32, r0 = blockIdx.y * 32;
#pragma unroll
    for (int i = 0; i < 32; i += 8)
        t[threadIdx.y + i][threadIdx.x] = in[(size_t)(r0 + threadIdx.y + i) * C + c0 + threadIdx.x];
    __syncthreads();
#pragma unroll
    for (int i = 0; i < 32; i += 8)
        out[(size_t)(c0 + threadIdx.y + i) * R + r0 + threadIdx.x] = rndf(t[threadIdx.x][threadIdx.y + i]);
}

// ---------------- out = xres + alpha*(a-mean)/(std_unbiased+eps) + beta ----------------
template <bool DUAL>
__global__ void add_ln(const float* __restrict__ xres, const float* __restrict__ a,
                       const float* __restrict__ alpha, const float* __restrict__ beta,
                       float* __restrict__ out, float* __restrict__ outr) {
    int row = blockIdx.x;
    int tid = threadIdx.x;
    const float* ap = a + (size_t)row * DD;
    float v[4];
    float lsum = 0.f;
#pragma unroll
    for (int i = 0; i < 4; i++) {
        v[i] = ap[tid + i * 256];
        lsum += v[i];
    }
    __shared__ float red[256];
    red[tid] = lsum;
    __syncthreads();
    for (int s = 128; s > 0; s >>= 1) {
        if (tid < s) red[tid] += red[tid + s];
        __syncthreads();
    }
    float mean = red[0] * (1.f / DD);
    __syncthreads();
    float lss = 0.f;
#pragma unroll
    for (int i = 0; i < 4; i++) {
        float d = v[i] - mean;
        lss += d * d;
    }
    red[tid] = lss;
    __syncthreads();
    for (int s = 128; s > 0; s >>= 1) {
        if (tid < s) red[tid] += red[tid + s];
        __syncthreads();
    }
    float var = red[0] * (1.f / (DD - 1));
    float inv = 1.f / (sqrtf(var) + 1e-6f);
#pragma unroll
    for (int i = 0; i < 4; i++) {
        int c = tid + i * 256;
        float o = xres[(size_t)row * DD + c] + alpha[c] * (v[i] - mean) * inv + beta[c];
        out[(size_t)row * DD + c] = o;
        if (DUAL) outr[(size_t)row * DD + c] = rndf(o);
    }
}

// ---------------- launch ----------------
extern "C" void kernel_launch(void* const* d_in, const int* in_sizes, int n_in,
                              void* d_out, int out_size) {
    const float* x      = (const float*)d_in[0];
    const int*   mask   = (const int*)d_in[1];
    const float* Wq     = (const float*)d_in[2];
    const float* bq     = (const float*)d_in[3];
    const float* Wk     = (const float*)d_in[4];
    const float* bk     = (const float*)d_in[5];
    const float* Wv     = (const float*)d_in[6];
    const float* bv     = (const float*)d_in[7];
    const float* W1     = (const float*)d_in[8];
    const float* b1     = (const float*)d_in[9];
    const float* W2     = (const float*)d_in[10];
    const float* b2     = (const float*)d_in[11];
    const float* alpha1 = (const float*)d_in[12];
    const float* beta1  = (const float*)d_in[13];
    const float* alpha2 = (const float*)d_in[14];
    const float* beta2  = (const float*)d_in[15];
    float* out = (float*)d_out;

    float *xr, *WpackT, *bpack, *W1T, *W2T, *QKV, *attn, *x1, *x1r, *h1, *ffn;
    cudaGetSymbolAddress((void**)&xr,     g_xr);
    cudaGetSymbolAddress((void**)&WpackT, g_WpackT);
    cudaGetSymbolAddress((void**)&bpack,  g_bpack);
    cudaGetSymbolAddress((void**)&W1T,    g_W1T);
    cudaGetSymbolAddress((void**)&W2T,    g_W2T);
    cudaGetSymbolAddress((void**)&QKV,    g_QKV);
    cudaGetSymbolAddress((void**)&attn,   g_attn);
    cudaGetSymbolAddress((void**)&x1,     g_x1);
    cudaGetSymbolAddress((void**)&x1r,    g_x1r);
    cudaGetSymbolAddress((void**)&h1,     g_h1);
    cudaGetSymbolAddress((void**)&ffn,    g_ffn);

    cudaFuncSetAttribute(mma_gemm<0, true>,  cudaFuncAttributeMaxDynamicSharedMemorySize, G_SMEM);
    cudaFuncSetAttribute(mma_gemm<0, false>, cudaFuncAttributeMaxDynamicSharedMemorySize, G_SMEM);
    cudaFuncSetAttribute(mma_gemm<1, true>,  cudaFuncAttributeMaxDynamicSharedMemorySize, G_SMEM);
    cudaFuncSetAttribute(flash_attn, cudaFuncAttributeMaxDynamicSharedMemorySize, FA_SMEM);

    // prep
    round_copy<<<(MTOK * DD / 4 + 255) / 256, 256>>>(x, xr, MTOK * DD / 4);
    pack_wT<<<dim3(32, 2, 48), dim3(32, 8)>>>(Wq, Wk, Wv);
    pack_bias<<<12, 256>>>(bq, bk, bv);
    transpose_k<<<dim3(DFF / 32, DD / 32), dim3(32, 8)>>>(W1, W1T, DD, DFF);
    transpose_k<<<dim3(DD / 32, DFF / 32), dim3(32, 8)>>>(W2, W2T, DFF, DD);

    // QKV = xr @ WpackT^T + bias  [4096, 3072], rounded
    mma_gemm<0, true><<<dim3(24, 16), 512, G_SMEM>>>(
        xr, DD, WpackT, DD, QKV, 3 * DD, bpack, DD);

    // fused attention: scores + mask + softmax + P@V
    flash_attn<<<dim3(8, 32), 256, FA_SMEM>>>(QKV, mask, attn);

    // x1 = x + LN1(attn)  (exact + rounded copy)
    add_ln<true><<<MTOK, 256>>>(x, attn, alpha1, beta1, x1, x1r);

    // FFN1: relu(x1r @ W1 + b1), rounded
    mma_gemm<1, true><<<dim3(32, 16), 512, G_SMEM>>>(
        x1r, DD, W1T, DD, h1, DFF, b1, DD);

    // FFN2: h1 @ W2 + b2
    mma_gemm<0, false><<<dim3(8, 16), 512, G_SMEM>>>(
        h1, DFF, W2T, DFF, ffn, DD, b2, DFF);

    // out = x1 + LN2(ffn)
    add_ln<false><<<MTOK, 256>>>(x1, ffn, alpha2, beta2, out, nullptr);
}

// round 8
// speedup vs baseline: 1.9516x; 1.9304x over previous
#include <cuda_runtime.h>
#include <cuda_fp16.h>
#include <math.h>
#include <stdint.h>

#define BB 2
#define SS 2048
#define DD 1024
#define HH 16
#define DFF 4096
#define MTOK 4096

// ---------------- scratch (no allocations allowed) ----------------
__device__ __half g_xr[(size_t)MTOK * DD];           // fp16 x
__device__ __half g_WpackT[(size_t)3 * DD * DD];     // [3D, D] K-major packed qkv weights
__device__ float  g_bpack[3 * DD];
__device__ __half g_W1T[(size_t)DFF * DD];           // [4D, D]
__device__ __half g_W2T[(size_t)DD * DFF];           // [D, 4D]
__device__ __half g_QKV[(size_t)MTOK * 3 * DD];      // [tok, 3D] fp16
__device__ float  g_attn[(size_t)MTOK * DD];
__device__ float  g_x1[(size_t)MTOK * DD];           // exact
__device__ __half g_x1r[(size_t)MTOK * DD];          // fp16
__device__ __half g_h1[(size_t)MTOK * DFF];          // fp16
__device__ float  g_ffn[(size_t)MTOK * DD];

// ---------------- helpers ----------------
__device__ __forceinline__ uint32_t smem_u32(const void* p) {
    uint32_t a;
    asm("{ .reg .u64 t; cvta.to.shared.u64 t, %1; cvt.u32.u64 %0, t; }" : "=r"(a) : "l"(p));
    return a;
}
__device__ __forceinline__ uint32_t packh2(float lo, float hi) {
    uint32_t u;
    asm("cvt.rn.f16x2.f32 %0, %1, %2;" : "=r"(u) : "f"(hi), "f"(lo));
    return u;
}
#define SWZ128(o) ((o) ^ (((o) >> 3) & 0x70))
#define CP16(dst, src) asm volatile("cp.async.cg.shared.global [%0], [%1], 16;" :: "r"(dst), "l"(src))
#define LDSM4(r0, r1, r2, r3, a) \
    asm volatile("ldmatrix.sync.aligned.m8n8.x4.shared.b16 {%0,%1,%2,%3}, [%4];" \
                 : "=r"(r0), "=r"(r1), "=r"(r2), "=r"(r3) : "r"(a))
#define LDSM4T(r0, r1, r2, r3, a) \
    asm volatile("ldmatrix.sync.aligned.m8n8.x4.trans.shared.b16 {%0,%1,%2,%3}, [%4];" \
                 : "=r"(r0), "=r"(r1), "=r"(r2), "=r"(r3) : "r"(a))

__device__ __forceinline__ void mma_f16(float* d, const uint32_t* a, uint32_t b0, uint32_t b1) {
    asm volatile(
        "mma.sync.aligned.m16n8k16.row.col.f32.f16.f16.f32 "
        "{%0,%1,%2,%3}, {%4,%5,%6,%7}, {%8,%9}, {%0,%1,%2,%3};"
        : "+f"(d[0]), "+f"(d[1]), "+f"(d[2]), "+f"(d[3])
        : "r"(a[0]), "r"(a[1]), "r"(a[2]), "r"(a[3]), "r"(b0), "r"(b1));
}

// ================= FLASH ATTENTION (fp16, 128 q-rows/CTA) =================
// grid (16 qtiles, 32 bh), block 256 (8 warps x 16 q-rows).
// SMEM: Q[128][64h] | K[2][128][64h] | V[2][128][64h] | mask[2048] (all 128B rows, SW128)
#define FK_BYTES 16384
#define FV_BYTES 16384
#define OFF_Q 0
#define OFF_K 16384
#define OFF_V 49152
#define OFF_M 81920
#define FA_SMEM 90112

__global__ void __launch_bounds__(256, 1)
flash_attn(const __half* __restrict__ QKV, const int* __restrict__ mask,
           float* __restrict__ out) {
    extern __shared__ char smem[];
    const uint32_t sb = smem_u32(smem);
    int tid = threadIdx.x, wid = tid >> 5, lid = tid & 31;
    int g = lid >> 2, tc = lid & 3;
    int qt = blockIdx.x, bh = blockIdx.y;
    int b = bh >> 4, h = bh & 15;
    int q0 = qt * 128;
    int wq0 = wid * 16;
    const __half* base = QKV + (size_t)b * SS * 3072 + h * 64;

    // ldmatrix lane addressing pieces
    int rA = (lid & 7) + ((lid >> 3) & 1) * 8;   // A/V row-group pattern
    int cA = lid >> 4;                            // A/V chunk pattern
    int rB = (lid & 7) + ((lid >> 4) & 1) * 8;   // B(K) row pattern
    int cB = (lid >> 3) & 1;                      // B(K) chunk pattern

    // ---- stage Q + K0 + V0 (each 128 rows x 8 x 16B) ----
#pragma unroll
    for (int i = 0; i < 4; i++) {
        int q = tid + i * 256, r = q >> 3, c = q & 7;
        CP16(sb + OFF_Q + SWZ128(q * 16), base + (size_t)(q0 + r) * 3072 + c * 8);
    }
#pragma unroll
    for (int i = 0; i < 4; i++) {
        int q = tid + i * 256, r = q >> 3, c = q & 7;
        CP16(sb + OFF_K + SWZ128(q * 16), base + (size_t)r * 3072 + 1024 + c * 8);
    }
#pragma unroll
    for (int i = 0; i < 4; i++) {
        int q = tid + i * 256, r = q >> 3, c = q & 7;
        CP16(sb + OFF_V + SWZ128(q * 16), base + (size_t)r * 3072 + 2048 + c * 8);
    }
    asm volatile("cp.async.commit_group;" ::: "memory");
    int* msmem = (int*)(smem + OFF_M);
#pragma unroll
    for (int i = 0; i < 8; i++) {
        int idx = tid + i * 256;
        msmem[idx] = mask[b * SS + idx];
    }
    asm volatile("cp.async.wait_group 0;" ::: "memory");
    __syncthreads();

    // ---- Q fragments (4 k16-steps, persist) ----
    uint32_t af[4][4];
#pragma unroll
    for (int s = 0; s < 4; s++) {
        uint32_t addr = sb + OFF_Q + SWZ128((wq0 + rA) * 128 + (2 * s + cA) * 16);
        LDSM4(af[s][0], af[s][1], af[s][2], af[s][3], addr);
    }

    float oacc[8][4];
#pragma unroll
    for (int i = 0; i < 8; i++)
#pragma unroll
        for (int j = 0; j < 4; j++) oacc[i][j] = 0.f;
    float l0 = 0.f, l1 = 0.f, m0 = -INFINITY, m1 = -INFINITY;

    for (int it = 0; it < 16; it++) {
        int buf = it & 1;
        if (it + 1 < 16) {
            int kv1 = (it + 1) * 128, nb = buf ^ 1;
#pragma unroll
            for (int i = 0; i < 4; i++) {
                int q = tid + i * 256, r = q >> 3, c = q & 7;
                CP16(sb + OFF_K + nb * FK_BYTES + SWZ128(q * 16),
                     base + (size_t)(kv1 + r) * 3072 + 1024 + c * 8);
            }
#pragma unroll
            for (int i = 0; i < 4; i++) {
                int q = tid + i * 256, r = q >> 3, c = q & 7;
                CP16(sb + OFF_V + nb * FV_BYTES + SWZ128(q * 16),
                     base + (size_t)(kv1 + r) * 3072 + 2048 + c * 8);
            }
            asm volatile("cp.async.commit_group;" ::: "memory");
        }
        if (it > 0) {
            if (it + 1 < 16) asm volatile("cp.async.wait_group 1;" ::: "memory");
            else             asm volatile("cp.async.wait_group 0;" ::: "memory");
            __syncthreads();
        }

        int kv0 = it * 128;
        uint32_t kb = sb + OFF_K + buf * FK_BYTES;
        uint32_t vb = sb + OFF_V + buf * FV_BYTES;

        // ---- S = Q @ K^T (8 n-pairs x 4 k16-steps) ----
        float sacc[16][4];
#pragma unroll
        for (int i = 0; i < 16; i++)
#pragma unroll
            for (int j = 0; j < 4; j++) sacc[i][j] = 0.f;
#pragma unroll
        for (int np = 0; np < 8; np++) {
            int nrow = 16 * np + rB;
#pragma unroll
            for (int s = 0; s < 4; s++) {
                uint32_t bq[4];
                LDSM4(bq[0], bq[1], bq[2], bq[3],
                      kb + SWZ128(nrow * 128 + (2 * s + cB) * 16));
                mma_f16(sacc[2 * np],     af[s], bq[0], bq[1]);
                mma_f16(sacc[2 * np + 1], af[s], bq[2], bq[3]);
            }
        }

        // ---- scale + mask + online softmax ----
        float mt0 = -INFINITY, mt1 = -INFINITY;
#pragma unroll
        for (int nt = 0; nt < 16; nt++) {
            int c0 = kv0 + 8 * nt + 2 * tc;
            int mk0 = msmem[c0], mk1 = msmem[c0 + 1];
            float s0 = sacc[nt][0] * 0.125f, s1 = sacc[nt][1] * 0.125f;
            float s2 = sacc[nt][2] * 0.125f, s3 = sacc[nt][3] * 0.125f;
            if (mk0 == 0) { s0 = -INFINITY; s2 = -INFINITY; }
            if (mk1 == 0) { s1 = -INFINITY; s3 = -INFINITY; }
            sacc[nt][0] = s0; sacc[nt][1] = s1; sacc[nt][2] = s2; sacc[nt][3] = s3;
            mt0 = fmaxf(mt0, fmaxf(s0, s1));
            mt1 = fmaxf(mt1, fmaxf(s2, s3));
        }
        mt0 = fmaxf(mt0, __shfl_xor_sync(0xffffffff, mt0, 1));
        mt0 = fmaxf(mt0, __shfl_xor_sync(0xffffffff, mt0, 2));
        mt1 = fmaxf(mt1, __shfl_xor_sync(0xffffffff, mt1, 1));
        mt1 = fmaxf(mt1, __shfl_xor_sync(0xffffffff, mt1, 2));
        float mn0 = fmaxf(m0, mt0), mn1 = fmaxf(m1, mt1);
        float al0 = __expf(m0 - mn0), al1 = __expf(m1 - mn1);
        l0 *= al0; l1 *= al1;
#pragma unroll
        for (int i = 0; i < 8; i++) {
            oacc[i][0] *= al0; oacc[i][1] *= al0;
            oacc[i][2] *= al1; oacc[i][3] *= al1;
        }
#pragma unroll
        for (int nt = 0; nt < 16; nt++) {
            float p0 = __expf(sacc[nt][0] - mn0);
            float p1 = __expf(sacc[nt][1] - mn0);
            float p2 = __expf(sacc[nt][2] - mn1);
            float p3 = __expf(sacc[nt][3] - mn1);
            l0 += p0 + p1; l1 += p2 + p3;
            sacc[nt][0] = p0; sacc[nt][1] = p1;
            sacc[nt][2] = p2; sacc[nt][3] = p3;
        }
        m0 = mn0; m1 = mn1;

        // ---- O += P @ V : P packs directly into A-fragments (no shuffles) ----
#pragma unroll
        for (int kc = 0; kc < 8; kc++) {
            uint32_t afr[4];
            afr[0] = packh2(sacc[2 * kc][0],     sacc[2 * kc][1]);
            afr[1] = packh2(sacc[2 * kc][2],     sacc[2 * kc][3]);
            afr[2] = packh2(sacc[2 * kc + 1][0], sacc[2 * kc + 1][1]);
            afr[3] = packh2(sacc[2 * kc + 1][2], sacc[2 * kc + 1][3]);
            int vrow = 16 * kc + rA;
#pragma unroll
            for (int np = 0; np < 4; np++) {
                uint32_t bv[4];
                LDSM4T(bv[0], bv[1], bv[2], bv[3],
                       vb + SWZ128(vrow * 128 + np * 32 + cA * 16));
                mma_f16(oacc[2 * np],     afr, bv[0], bv[1]);
                mma_f16(oacc[2 * np + 1], afr, bv[2], bv[3]);
            }
        }
        __syncthreads();
    }

    // ---- reduce l across quad ----
    l0 += __shfl_xor_sync(0xffffffff, l0, 1);
    l0 += __shfl_xor_sync(0xffffffff, l0, 2);
    l1 += __shfl_xor_sync(0xffffffff, l1, 1);
    l1 += __shfl_xor_sync(0xffffffff, l1, 2);

    // ---- epilogue: O / l -> attn [tok, D] fp32 ----
    float il0 = 1.f / l0, il1 = 1.f / l1;
    int r0 = q0 + wq0 + g, r1 = r0 + 8;
    float* o0 = out + (size_t)(b * SS + r0) * DD + h * 64 + 2 * tc;
    float* o1 = out + (size_t)(b * SS + r1) * DD + h * 64 + 2 * tc;
#pragma unroll
    for (int nt = 0; nt < 8; nt++) {
        *(float2*)(o0 + nt * 8) = make_float2(oacc[nt][0] * il0, oacc[nt][1] * il0);
        *(float2*)(o1 + nt * 8) = make_float2(oacc[nt][2] * il1, oacc[nt][3] * il1);
    }
}

// ---------------- fp16 mma GEMM: 256x128 tile, BK=64, 512 threads ----------------
// C[M,N] = A[M,K] @ B[N,K]^T + epilogue.  MODE 0: +bias  1: relu(+bias)
// WH: write half output (else float)
#define GA_BYTES 32768
#define GB_BYTES 16384
#define G_SMEM (2 * GA_BYTES + 2 * GB_BYTES)

template <int MODE, bool WH>
__global__ void __launch_bounds__(512)
mma_gemm(const __half* __restrict__ A, int lda,
         const __half* __restrict__ B, int ldb,
         void* __restrict__ Cv, int ldc,
         const float* __restrict__ bias, int K) {
    extern __shared__ char smem[];
    const uint32_t sb = smem_u32(smem);
    int tid = threadIdx.x, wid = tid >> 5, lid = tid & 31;
    int m0 = blockIdx.y * 256, n0 = blockIdx.x * 128;
    int wm0 = (wid >> 2) * 64, wn0 = (wid & 3) * 32;

    int rA = (lid & 7) + ((lid >> 3) & 1) * 8;
    int cA = lid >> 4;
    int rB = (lid & 7) + ((lid >> 4) & 1) * 8;
    int cB = (lid >> 3) & 1;

    float acc[4][4][4];
#pragma unroll
    for (int i = 0; i < 4; i++)
#pragma unroll
        for (int j = 0; j < 4; j++)
#pragma unroll
            for (int r = 0; r < 4; r++) acc[i][j][r] = 0.f;

    const int NC = K >> 6;
    {
        uint32_t ab = sb, bb = sb + 2 * GA_BYTES;
#pragma unroll
        for (int i = 0; i < 4; i++) {
            int q = tid + i * 512, row = q >> 3, cg = q & 7;
            CP16(ab + SWZ128(q * 16), A + (size_t)(m0 + row) * lda + cg * 8);
        }
#pragma unroll
        for (int i = 0; i < 2; i++) {
            int q = tid + i * 512, row = q >> 3, cg = q & 7;
            CP16(bb + SWZ128(q * 16), B + (size_t)(n0 + row) * ldb + cg * 8);
        }
        asm volatile("cp.async.commit_group;" ::: "memory");
    }

    for (int c = 0; c < NC; c++) {
        int buf = c & 1;
        if (c + 1 < NC) {
            int k0 = (c + 1) << 6;
            uint32_t ab = sb + (buf ^ 1) * GA_BYTES;
            uint32_t bb = sb + 2 * GA_BYTES + (buf ^ 1) * GB_BYTES;
#pragma unroll
            for (int i = 0; i < 4; i++) {
                int q = tid + i * 512, row = q >> 3, cg = q & 7;
                CP16(ab + SWZ128(q * 16), A + (size_t)(m0 + row) * lda + k0 + cg * 8);
            }
#pragma unroll
            for (int i = 0; i < 2; i++) {
                int q = tid + i * 512, row = q >> 3, cg = q & 7;
                CP16(bb + SWZ128(q * 16), B + (size_t)(n0 + row) * ldb + k0 + cg * 8);
            }
            asm volatile("cp.async.commit_group;" ::: "memory");
            asm volatile("cp.async.wait_group 1;" ::: "memory");
        } else {
            asm volatile("cp.async.wait_group 0;" ::: "memory");
        }
        __syncthreads();

        uint32_t ab = sb + buf * GA_BYTES;
        uint32_t bb = sb + 2 * GA_BYTES + buf * GB_BYTES;
#pragma unroll
        for (int s = 0; s < 4; s++) {
            uint32_t af[4][4];
#pragma unroll
            for (int mt = 0; mt < 4; mt++) {
                int row = wm0 + mt * 16 + rA;
                LDSM4(af[mt][0], af[mt][1], af[mt][2], af[mt][3],
                      ab + SWZ128(row * 128 + (2 * s + cA) * 16));
            }
            uint32_t bfr[8];
#pragma unroll
            for (int pr = 0; pr < 2; pr++) {
                int row = wn0 + pr * 16 + rB;
                LDSM4(bfr[4 * pr], bfr[4 * pr + 1], bfr[4 * pr + 2], bfr[4 * pr + 3],
                      bb + SWZ128(row * 128 + (2 * s + cB) * 16));
            }
#pragma unroll
            for (int mt = 0; mt < 4; mt++) {
#pragma unroll
                for (int nt = 0; nt < 4; nt++)
                    mma_f16(acc[mt][nt], af[mt], bfr[2 * nt], bfr[2 * nt + 1]);
            }
        }
        __syncthreads();
    }

    int g = lid >> 2, tc = lid & 3;
#pragma unroll
    for (int mt = 0; mt < 4; mt++) {
        int row = m0 + wm0 + mt * 16 + g;
#pragma unroll
        for (int nt = 0; nt < 4; nt++) {
            int col = n0 + wn0 + nt * 8 + tc * 2;
            float v00 = acc[mt][nt][0], v01 = acc[mt][nt][1];
            float v10 = acc[mt][nt][2], v11 = acc[mt][nt][3];
            float2 bv = *(const float2*)(bias + col);
            v00 += bv.x; v01 += bv.y; v10 += bv.x; v11 += bv.y;
            if (MODE == 1) {
                v00 = fmaxf(v00, 0.f); v01 = fmaxf(v01, 0.f);
                v10 = fmaxf(v10, 0.f); v11 = fmaxf(v11, 0.f);
            }
            if (WH) {
                __half* C = (__half*)Cv;
                *(uint32_t*)(C + (size_t)row * ldc + col) = packh2(v00, v01);
                *(uint32_t*)(C + (size_t)(row + 8) * ldc + col) = packh2(v10, v11);
            } else {
                float* C = (float*)Cv;
                *(float2*)(C + (size_t)row * ldc + col) = make_float2(v00, v01);
                *(float2*)(C + (size_t)(row + 8) * ldc + col) = make_float2(v10, v11);
            }
        }
    }
}

// ---------------- prep kernels ----------------
__global__ void round_copy(const float* __restrict__ in, __half* __restrict__ out, int n4) {
    int i = blockIdx.x * blockDim.x + threadIdx.x;
    if (i < n4) {
        float4 v = ((const float4*)in)[i];
        uint32_t* o = (uint32_t*)out;
        o[2 * i]     = packh2(v.x, v.y);
        o[2 * i + 1] = packh2(v.z, v.w);
    }
}

__global__ void pack_wT(const float* __restrict__ Wq, const float* __restrict__ Wk,
                        const float* __restrict__ Wv) {
    __shared__ float t[32][33];
    int zz = blockIdx.z;
    int which = zz / HH, h = zz % HH;
    const float* W = (which == 0) ? Wq : (which == 1) ? Wk : Wv;
    int d0 = blockIdx.x * 32, e0 = blockIdx.y * 32;
#pragma unroll
    for (int i = 0; i < 32; i += 8)
        t[threadIdx.y + i][threadIdx.x] =
            W[(size_t)h * (DD * 64) + (size_t)(d0 + threadIdx.y + i) * 64 + e0 + threadIdx.x];
    __syncthreads();
#pragma unroll
    for (int i = 0; i < 32; i += 8)
        g_WpackT[(size_t)(which * DD + h * 64 + e0 + threadIdx.y + i) * DD + d0 + threadIdx.x] =
            __float2half_rn(t[threadIdx.x][threadIdx.y + i]);
}

__global__ void pack_bias(const float* __restrict__ bq, const float* __restrict__ bk,
                          const float* __restrict__ bv) {
    int i = blockIdx.x * blockDim.x + threadIdx.x;
    if (i < 3 * DD) {
        int which = i / DD, c = i % DD;
        const float* b = (which == 0) ? bq : (which == 1) ? bk : bv;
        g_bpack[i] = b[c];
    }
}

__global__ void transpose_k(const float* __restrict__ in, __half* __restrict__ out, int R, int C) {
    __shared__ float t[32][33];
    int c0 = blockIdx.x * 32, r0 = blockIdx.y * 32;
#pragma unroll
    for (int i = 0; i < 32; i += 8)
        t[threadIdx.y + i][threadIdx.x] = in[(size_t)(r0 + threadIdx.y + i) * C + c0 + threadIdx.x];
    __syncthreads();
#pragma unroll
    for (int i = 0; i < 32; i += 8)
        out[(size_t)(c0 + threadIdx.y + i) * R + r0 + threadIdx.x] =
            __float2half_rn(t[threadIdx.x][threadIdx.y + i]);
}

// ---------------- out = xres + alpha*(a-mean)/(std_unbiased+eps) + beta ----------------
template <bool DUAL>
__global__ void add_ln(const float* __restrict__ xres, const float* __restrict__ a,
                       const float* __restrict__ alpha, const float* __restrict__ beta,
                       float* __restrict__ out, __half* __restrict__ outr) {
    int row = blockIdx.x;
    int tid = threadIdx.x;
    const float* ap = a + (size_t)row * DD;
    float v[4];
    float lsum = 0.f;
#pragma unroll
    for (int i = 0; i < 4; i++) {
        v[i] = ap[tid + i * 256];
        lsum += v[i];
    }
    __shared__ float red[256];
    red[tid] = lsum;
    __syncthreads();
    for (int s = 128; s > 0; s >>= 1) {
        if (tid < s) red[tid] += red[tid + s];
        __syncthreads();
    }
    float mean = red[0] * (1.f / DD);
    __syncthreads();
    float lss = 0.f;
#pragma unroll
    for (int i = 0; i < 4; i++) {
        float d = v[i] - mean;
        lss += d * d;
    }
    red[tid] = lss;
    __syncthreads();
    for (int s = 128; s > 0; s >>= 1) {
        if (tid < s) red[tid] += red[tid + s];
        __syncthreads();
    }
    float var = red[0] * (1.f / (DD - 1));
    float inv = 1.f / (sqrtf(var) + 1e-6f);
#pragma unroll
    for (int i = 0; i < 4; i++) {
        int c = tid + i * 256;
        float o = xres[(size_t)row * DD + c] + alpha[c] * (v[i] - mean) * inv + beta[c];
        out[(size_t)row * DD + c] = o;
        if (DUAL) outr[(size_t)row * DD + c] = __float2half_rn(o);
    }
}

// ---------------- launch ----------------
extern "C" void kernel_launch(void* const* d_in, const int* in_sizes, int n_in,
                              void* d_out, int out_size) {
    const float* x      = (const float*)d_in[0];
    const int*   mask   = (const int*)d_in[1];
    const float* Wq     = (const float*)d_in[2];
    const float* bq     = (const float*)d_in[3];
    const float* Wk     = (const float*)d_in[4];
    const float* bk     = (const float*)d_in[5];
    const float* Wv     = (const float*)d_in[6];
    const float* bv     = (const float*)d_in[7];
    const float* W1     = (const float*)d_in[8];
    const float* b1     = (const float*)d_in[9];
    const float* W2     = (const float*)d_in[10];
    const float* b2     = (const float*)d_in[11];
    const float* alpha1 = (const float*)d_in[12];
    const float* beta1  = (const float*)d_in[13];
    const float* alpha2 = (const float*)d_in[14];
    const float* beta2  = (const float*)d_in[15];
    float* out = (float*)d_out;

    __half *xr, *WpackT, *W1T, *W2T, *QKV, *x1r, *h1;
    float *bpack, *attn, *x1, *ffn;
    cudaGetSymbolAddress((void**)&xr,     g_xr);
    cudaGetSymbolAddress((void**)&WpackT, g_WpackT);
    cudaGetSymbolAddress((void**)&bpack,  g_bpack);
    cudaGetSymbolAddress((void**)&W1T,    g_W1T);
    cudaGetSymbolAddress((void**)&W2T,    g_W2T);
    cudaGetSymbolAddress((void**)&QKV,    g_QKV);
    cudaGetSymbolAddress((void**)&attn,   g_attn);
    cudaGetSymbolAddress((void**)&x1,     g_x1);
    cudaGetSymbolAddress((void**)&x1r,    g_x1r);
    cudaGetSymbolAddress((void**)&h1,     g_h1);
    cudaGetSymbolAddress((void**)&ffn,    g_ffn);

    cudaFuncSetAttribute(mma_gemm<0, true>,  cudaFuncAttributeMaxDynamicSharedMemorySize, G_SMEM);
    cudaFuncSetAttribute(mma_gemm<1, true>,  cudaFuncAttributeMaxDynamicSharedMemorySize, G_SMEM);
    cudaFuncSetAttribute(mma_gemm<0, false>, cudaFuncAttributeMaxDynamicSharedMemorySize, G_SMEM);
    cudaFuncSetAttribute(flash_attn, cudaFuncAttributeMaxDynamicSharedMemorySize, FA_SMEM);

    // prep
    round_copy<<<(MTOK * DD / 4 + 255) / 256, 256>>>(x, xr, MTOK * DD / 4);
    pack_wT<<<dim3(32, 2, 48), dim3(32, 8)>>>(Wq, Wk, Wv);
    pack_bias<<<12, 256>>>(bq, bk, bv);
    transpose_k<<<dim3(DFF / 32, DD / 32), dim3(32, 8)>>>(W1, W1T, DD, DFF);
    transpose_k<<<dim3(DD / 32, DFF / 32), dim3(32, 8)>>>(W2, W2T, DFF, DD);

    // QKV = xr @ WpackT^T + bias  [4096, 3072] fp16 out
    mma_gemm<0, true><<<dim3(24, 16), 512, G_SMEM>>>(
        xr, DD, WpackT, DD, QKV, 3 * DD, bpack, DD);

    // fused attention: scores + mask + softmax + P@V (fp16 mma, fp32 out)
    flash_attn<<<dim3(16, 32), 256, FA_SMEM>>>(QKV, mask, attn);

    // x1 = x + LN1(attn)  (fp32 + fp16 copy)
    add_ln<true><<<MTOK, 256>>>(x, attn, alpha1, beta1, x1, x1r);

    // FFN1: relu(x1r @ W1 + b1) fp16 out
    mma_gemm<1, true><<<dim3(32, 16), 512, G_SMEM>>>(
        x1r, DD, W1T, DD, h1, DFF, b1, DD);

    // FFN2: h1 @ W2 + b2  fp32 out
    mma_gemm<0, false><<<dim3(8, 16), 512, G_SMEM>>>(
        h1, DFF, W2T, DFF, ffn, DD, b2, DFF);

    // out = x1 + LN2(ffn)
    add_ln<false><<<MTOK, 256>>>(x1, ffn, alpha2, beta2, out, nullptr);
}